// round 9
// baseline (speedup 1.0000x reference)
#include <cuda_runtime.h>
#include <math.h>

#define H 64
#define W 64
#define C 256
#define P 7
#define NUM_ROIS 256
#define FC (W * C)   // floats per x-row (16384)

// Precomputed bin bounds: [roi][axis][bin] -> {start, len}
// axis 0 = x (H, i), axis 1 = y (W, j)
__device__ int2 g_xbins[NUM_ROIS * P];
__device__ int2 g_ybins[NUM_ROIS * P];

__device__ __forceinline__ float4 fmax4(float4 a, float4 b) {
    a.x = fmaxf(a.x, b.x);
    a.y = fmaxf(a.y, b.y);
    a.z = fmaxf(a.z, b.z);
    a.w = fmaxf(a.w, b.w);
    return a;
}

// Setup: 3584 entries = 256 rois x 14 (7 x-bins, 7 y-bins). Exact reference
// math: lo=floor(lo_f*size), hi=ceil(hi_f*size), span=max(hi-lo,1),
// start=lo+floor(k*span/P), end=lo+ceil((k+1)*span/P), len=max(end-start,1),
// start clipped to [0,size-1].
__global__ __launch_bounds__(128) void roi_bins_kernel(
    const float* __restrict__ rois)
{
    const int idx = blockIdx.x * 128 + (int)threadIdx.x;  // [0, 3584)
    if (idx >= NUM_ROIS * 14) return;
    const int r = idx / 14;
    const int k = idx - r * 14;
    const bool isx = (k < P);
    const int bin  = isx ? k : k - P;

    const float lo_f = __ldg(&rois[r * 4 + (isx ? 0 : 1)]);
    const float hi_f = __ldg(&rois[r * 4 + (isx ? 2 : 3)]);
    const int size = isx ? H : W;   // both 64

    const int lo   = (int)floorf(lo_f * (float)size);
    const int hi   = (int)ceilf(hi_f * (float)size);
    const int span = max(hi - lo, 1);
    int start      = lo + (bin * span) / P;
    const int end  = lo + ((bin + 1) * span + (P - 1)) / P;
    const int len  = max(end - start, 1);
    start = min(max(start, 0), size - 1);

    const int2 v = make_int2(start, len);
    if (isx) g_xbins[r * P + bin] = v;
    else     g_ybins[r * P + bin] = v;
}

// Main: one block per (roi, ij) bin; 64 threads = 64 float4 channel groups.
// gridDim = (49, 256): blockIdx.y = roi, blockIdx.x = i*7+j (no divisions).
// Prologue = two independent LDG.64 table reads. y-loop: ylen/2 clean pairs
// + warp-uniform odd tail (zero duplicate loads).
__global__ __launch_bounds__(64) void roi_pool_kernel(
    const float* __restrict__ feat,   // (H, W, C)
    float* __restrict__ out)          // (NUM_ROIS, P, P, C)
{
    const int ij = blockIdx.x;        // i*7 + j
    const int r  = blockIdx.y;
    const int i  = ij / P;            // mul-shift, cheap
    const int j  = ij - i * P;

    const int c4 = (int)threadIdx.x << 2;   // channel quad

    const int2 xb = g_xbins[r * P + i];     // {xs, xlen}
    const int2 yb = g_ybins[r * P + j];     // {ys, ylen}

    const int  npairs = yb.y >> 1;
    const bool ytail  = (yb.y & 1) != 0;
    const int  tailo  = (npairs * 2) * C;

    const float NEG = -INFINITY;
    float4 acc = make_float4(NEG, NEG, NEG, NEG);

    const float* rowp = feat + (size_t)xb.x * FC + (size_t)yb.x * C + c4;

    for (int sx = 0; sx < xb.y; ++sx) {
        const float* p = rowp;
        for (int sp = 0; sp < npairs; ++sp) {
            const float4 v0 = *reinterpret_cast<const float4*>(p);
            const float4 v1 = *reinterpret_cast<const float4*>(p + C);
            acc = fmax4(acc, fmax4(v0, v1));
            p += 2 * C;
        }
        if (ytail) {
            acc = fmax4(acc, *reinterpret_cast<const float4*>(rowp + tailo));
        }
        rowp += FC;
    }

    float* op = out + (((size_t)r * (P * P) + ij) * C) + c4;
    *reinterpret_cast<float4*>(op) = acc;
}

extern "C" void kernel_launch(void* const* d_in, const int* in_sizes, int n_in,
                              void* d_out, int out_size) {
    const float* feat = (const float*)d_in[0];
    const float* rois = (const float*)d_in[1];
    if (n_in >= 2 && in_sizes[0] == NUM_ROIS * 4 && in_sizes[1] == H * W * C) {
        feat = (const float*)d_in[1];
        rois = (const float*)d_in[0];
    }
    float* out = (float*)d_out;

    roi_bins_kernel<<<(NUM_ROIS * 14 + 127) / 128, 128>>>(rois);
    roi_pool_kernel<<<dim3(P * P, NUM_ROIS), 64>>>(feat, out);
}